// round 12
// baseline (speedup 1.0000x reference)
#include <cuda_runtime.h>
#include <cuda_fp16.h>
#include <math.h>

#define Bb 16
#define Ss 512
#define Tt 512
#define Dd 512
#define Rr 8
#define NEG_BIG (-1e10f)
#define LOG2E 1.4426950408889634f
#define NBLK 128

typedef unsigned long long u64;

// scratch (device globals; no allocation allowed)
__device__ float    g_src_wt[Bb * Rr * Ss];   // [b,r,s]
__device__ float    g_tar_wt[Bb * Rr * Tt];   // [b,r,t]
__device__ unsigned g_bar = 0;                // monotonic grid-barrier ticket

__device__ __forceinline__ float ex2(float x) {
    float y;
    asm("ex2.approx.f32 %0, %1;" : "=f"(y) : "f"(x));
    return y;
}
__device__ __forceinline__ u64 pk(float lo, float hi) {
    u64 d; asm("mov.b64 %0, {%1, %2};" : "=l"(d) : "f"(lo), "f"(hi)); return d;
}
__device__ __forceinline__ void upk(u64 p, float& lo, float& hi) {
    asm("mov.b64 {%0, %1}, %2;" : "=f"(lo), "=f"(hi) : "l"(p));
}
__device__ __forceinline__ u64 ffma2(u64 a, u64 b, u64 c) {
    u64 d; asm("fma.rn.f32x2 %0, %1, %2, %3;" : "=l"(d) : "l"(a), "l"(b), "l"(c)); return d;
}
__device__ __forceinline__ __half2 hex2(__half2 x) {
    unsigned u = *reinterpret_cast<unsigned*>(&x);
    unsigned y;
    asm("ex2.approx.f16x2 %0, %1;" : "=r"(y) : "r"(u));
    return *reinterpret_cast<__half2*>(&y);
}

// ---------------------------------------------------------------------------
// Single fused kernel: 128 blocks x 512 threads, guaranteed co-resident
// (launch_bounds(512,1): worst case 1 block/SM on 148 SMs >= 128 blocks).
// Phase 1 (dots): 128 rows/block (2 passes x 16 warps x 4 rows), raw-w dots
//   scaled by 1/||w_r|| at store. Phase boundary: threadfence + atomic-ticket
//   grid barrier (monotonic, replay-safe). Phase 2 (attn+out): s-tile 64,
//   thread (r=tid>>6, j=tid&63) does the full 512-t softmax-weighted sum with
//   the f16x2 fast path (vd = v - vmax/vmin; midpoint flush keeps 16 summands
//   per fp16 lane), then out tile [64 s][512 d] = c . (w * sc).
// ---------------------------------------------------------------------------
__global__ __launch_bounds__(512, 1) void k_fused(const float* __restrict__ src,
                                                  const float* __restrict__ tar,
                                                  const float* __restrict__ src_mask,
                                                  const float* __restrict__ tar_mask,
                                                  const float* __restrict__ w,
                                                  float* __restrict__ out) {
    __shared__ float   v_s[Rr * Tt];        // 16 KB (phase1: raw w overlay)
    __shared__ __half2 vdx_h[Rr * Tt / 2];  // 8 KB
    __shared__ __half2 vdn_h[Rr * Tt / 2];  // 8 KB
    __shared__ float   tm_s[Tt];            // 2 KB
    __shared__ float   a_s[Rr * 64];        // 2 KB
    __shared__ float   sm_s[64];
    __shared__ float   c_s[64 * Rr];        // 2 KB
    __shared__ float   sc_s[Rr];
    __shared__ float   red_max[Rr], red_min[Rr];
    __shared__ int     red_one[2];

    int tid  = threadIdx.x;
    int warp = tid >> 5;
    int lane = tid & 31;

    // ================= Phase 1: dots =================
    {
        float4* wn_s = (float4*)v_s;   // 16 KB raw w
        wn_s[tid]       = ((const float4*)w)[tid];
        wn_s[tid + 512] = ((const float4*)w)[tid + 512];
        __syncthreads();

        if (warp < Rr) {
            float ss = 0.f;
#pragma unroll
            for (int k = 0; k < 4; k++) {
                float4 x = wn_s[warp * 128 + lane + 32 * k];
                ss += x.x * x.x + x.y * x.y + x.z * x.z + x.w * x.w;
            }
#pragma unroll
            for (int off = 16; off; off >>= 1)
                ss += __shfl_xor_sync(0xffffffffu, ss, off);
            if (lane == 0) sc_s[warp] = 1.0f / fmaxf(sqrtf(ss), 1e-12f);
        }
        __syncthreads();

#pragma unroll
        for (int pass = 0; pass < 2; pass++) {
            int base = blockIdx.x * 128 + pass * 64 + warp * 4;
            bool is_src = base < Bb * Ss;          // 8192 % 128 == 0: no straddle
            const float* eb = is_src ? src : tar;
            int lbase = is_src ? base : base - Bb * Ss;

            u64 acc2[4][Rr];
#pragma unroll
            for (int rr = 0; rr < 4; rr++)
#pragma unroll
                for (int r = 0; r < Rr; r++) acc2[rr][r] = 0ull;

            float4 xa[4], xb[4];
#pragma unroll
            for (int rr = 0; rr < 4; rr++)
                xa[rr] = ((const float4*)(eb + (size_t)(lbase + rr) * Dd))[lane];

#pragma unroll
            for (int k = 0; k < 4; k++) {
                if (k < 3) {
#pragma unroll
                    for (int rr = 0; rr < 4; rr++)
                        xb[rr] = ((const float4*)(eb + (size_t)(lbase + rr) * Dd))[lane + 32 * (k + 1)];
                }
                u64 xp01[4], xp23[4];
#pragma unroll
                for (int rr = 0; rr < 4; rr++) {
                    xp01[rr] = pk(xa[rr].x, xa[rr].y);
                    xp23[rr] = pk(xa[rr].z, xa[rr].w);
                }
#pragma unroll
                for (int r = 0; r < Rr; r++) {
                    float4 wv = wn_s[r * 128 + lane + 32 * k];
                    u64 w01 = pk(wv.x, wv.y);
                    u64 w23 = pk(wv.z, wv.w);
#pragma unroll
                    for (int rr = 0; rr < 4; rr++) {
                        acc2[rr][r] = ffma2(xp01[rr], w01, acc2[rr][r]);
                        acc2[rr][r] = ffma2(xp23[rr], w23, acc2[rr][r]);
                    }
                }
#pragma unroll
                for (int rr = 0; rr < 4; rr++) xa[rr] = xb[rr];
            }

            // fold even/odd, butterfly so acc-index L lands at lane L
            float t[32];
#pragma unroll
            for (int rr = 0; rr < 4; rr++)
#pragma unroll
                for (int r = 0; r < Rr; r++) {
                    float lo, hi;
                    upk(acc2[rr][r], lo, hi);
                    t[rr * 8 + r] = lo + hi;
                }

#pragma unroll
            for (int st = 0; st < 5; st++) {
                int off = 1 << st;
                int sel = lane & off;
#pragma unroll
                for (int jj = 0; jj < (16 >> st); jj++) {
                    float give = sel ? t[2 * jj]     : t[2 * jj + 1];
                    float keep = sel ? t[2 * jj + 1] : t[2 * jj];
                    float recv = __shfl_xor_sync(0xffffffffu, give, off);
                    t[jj] = keep + recv;
                }
            }

            {
                int rr = lane >> 3, r = lane & 7;
                int gid = lbase + rr;
                int bb = gid >> 9, s = gid & 511;
                float* gw = is_src ? g_src_wt : g_tar_wt;
                gw[((size_t)bb * Rr + r) * Ss + s] = t[0] * sc_s[r];
            }
        }
    }

    // ================= Grid barrier =================
    __syncthreads();
    __threadfence();
    if (tid == 0) {
        unsigned ticket = atomicAdd(&g_bar, 1u);
        unsigned target = (ticket / NBLK + 1u) * NBLK;
        while (*(volatile unsigned*)&g_bar < target) { }
    }
    __syncthreads();

    // ================= Phase 2: attention + output =================
    int b  = blockIdx.x >> 3;
    int s0 = (blockIdx.x & 7) * 64;
    int r  = tid >> 6;
    int j  = tid & 63;

    const float4* vsrc = (const float4*)(g_tar_wt + (size_t)b * Rr * Tt);
    ((float4*)v_s)[tid]       = vsrc[tid];
    ((float4*)v_s)[tid + 512] = vsrc[tid + 512];
    if (tid < 128) ((float4*)tm_s)[tid] = ((const float4*)(tar_mask + (size_t)b * Tt))[tid];
    a_s[tid] = g_src_wt[((size_t)b * Rr + r) * Ss + s0 + j];
    if (tid < 64) sm_s[tid] = src_mask[(size_t)b * Ss + s0 + tid];
    __syncthreads();

    if (warp < Rr) {
        float cmax = -3.4e38f, cmin = 3.4e38f;
#pragma unroll
        for (int k = 0; k < 16; k++) {
            float v = v_s[warp * 512 + lane + 32 * k];
            cmax = fmaxf(cmax, v);
            cmin = fminf(cmin, v);
        }
#pragma unroll
        for (int off = 16; off; off >>= 1) {
            cmax = fmaxf(cmax, __shfl_xor_sync(0xffffffffu, cmax, off));
            cmin = fminf(cmin, __shfl_xor_sync(0xffffffffu, cmin, off));
        }
        if (lane == 0) { red_max[warp] = cmax; red_min[warp] = cmin; }
    } else if (warp == 8) {
        int one = 1;
#pragma unroll
        for (int k = 0; k < 16; k++)
            one &= (tm_s[lane + 32 * k] == 1.0f);
        one = (__ballot_sync(0xffffffffu, one) == 0xffffffffu);
        if (lane == 0) red_one[0] = one;
    } else if (warp == 9) {
        int one = (sm_s[lane] == 1.0f) & (sm_s[lane + 32] == 1.0f);
        one = (__ballot_sync(0xffffffffu, one) == 0xffffffffu);
        if (lane == 0) red_one[1] = one;
    }
    __syncthreads();

    int fast = red_one[0] & red_one[1];

    // build half2 vd arrays (2 float4 per thread per array)
#pragma unroll
    for (int i = tid; i < Rr * Tt / 4; i += 512) {
        float4 v4 = ((const float4*)v_s)[i];
        int rr = i >> 7;
        float mx = red_max[rr], mn = red_min[rr];
        vdx_h[2 * i]     = __floats2half2_rn(v4.x - mx, v4.y - mx);
        vdx_h[2 * i + 1] = __floats2half2_rn(v4.z - mx, v4.w - mx);
        vdn_h[2 * i]     = __floats2half2_rn(v4.x - mn, v4.y - mn);
        vdn_h[2 * i + 1] = __floats2half2_rn(v4.z - mn, v4.w - mn);
    }
    __syncthreads();

    float a = a_s[tid];
    float S = 0.f, A = 0.f;

    if (fast) {
        const uint4* vp = (const uint4*)((a >= 0.f) ? vdx_h : vdn_h) + r * 64;
        __half2 a2h = __half2half2(__float2half_rn(a * LOG2E));
#pragma unroll
        for (int hq = 0; hq < 2; hq++) {
            const uint4* vq = vp + hq * 32;
            __half2 sh[8], qh[8];
#pragma unroll
            for (int i = 0; i < 8; i++) { sh[i] = __half2half2(__ushort_as_half(0)); qh[i] = sh[i]; }
#pragma unroll
            for (int it = 0; it < 32; it += 2) {
                uint4 u0 = vq[it];
                uint4 u1 = vq[it + 1];
                __half2 v0 = *reinterpret_cast<__half2*>(&u0.x);
                __half2 v1 = *reinterpret_cast<__half2*>(&u0.y);
                __half2 v2 = *reinterpret_cast<__half2*>(&u0.z);
                __half2 v3 = *reinterpret_cast<__half2*>(&u0.w);
                __half2 e0 = hex2(__hmul2(a2h, v0));
                __half2 e1 = hex2(__hmul2(a2h, v1));
                __half2 e2 = hex2(__hmul2(a2h, v2));
                __half2 e3 = hex2(__hmul2(a2h, v3));
                sh[0] = __hadd2(sh[0], e0);
                sh[1] = __hadd2(sh[1], e1);
                sh[2] = __hadd2(sh[2], e2);
                sh[3] = __hadd2(sh[3], e3);
                qh[0] = __hfma2(e0, v0, qh[0]);
                qh[1] = __hfma2(e1, v1, qh[1]);
                qh[2] = __hfma2(e2, v2, qh[2]);
                qh[3] = __hfma2(e3, v3, qh[3]);
                __half2 w0 = *reinterpret_cast<__half2*>(&u1.x);
                __half2 w1 = *reinterpret_cast<__half2*>(&u1.y);
                __half2 w2 = *reinterpret_cast<__half2*>(&u1.z);
                __half2 w3 = *reinterpret_cast<__half2*>(&u1.w);
                __half2 f0 = hex2(__hmul2(a2h, w0));
                __half2 f1 = hex2(__hmul2(a2h, w1));
                __half2 f2 = hex2(__hmul2(a2h, w2));
                __half2 f3 = hex2(__hmul2(a2h, w3));
                sh[4] = __hadd2(sh[4], f0);
                sh[5] = __hadd2(sh[5], f1);
                sh[6] = __hadd2(sh[6], f2);
                sh[7] = __hadd2(sh[7], f3);
                qh[4] = __hfma2(f0, w0, qh[4]);
                qh[5] = __hfma2(f1, w1, qh[5]);
                qh[6] = __hfma2(f2, w2, qh[6]);
                qh[7] = __hfma2(f3, w3, qh[7]);
            }
#pragma unroll
            for (int i = 0; i < 8; i++) {
                float2 fs = __half22float2(sh[i]);
                float2 fq = __half22float2(qh[i]);
                S += fs.x + fs.y;
                A += fq.x + fq.y;
            }
        }
        float c = A / S + ((a >= 0.f) ? red_max[r] : red_min[r]);
        c_s[j * Rr + r] = c;
    } else {
        const float4* vv = (const float4*)(v_s + r * Tt);
        const float4* tt = (const float4*)tm_s;
        float sm = sm_s[j];
        float m = -3.4e38f;
#pragma unroll 4
        for (int t4 = 0; t4 < 128; t4++) {
            float4 v = vv[t4], tm = tt[t4];
            float x0 = fmaf(a, v.x, fmaf(sm * tm.x, 1e10f, NEG_BIG));
            float x1 = fmaf(a, v.y, fmaf(sm * tm.y, 1e10f, NEG_BIG));
            float x2 = fmaf(a, v.z, fmaf(sm * tm.z, 1e10f, NEG_BIG));
            float x3 = fmaf(a, v.w, fmaf(sm * tm.w, 1e10f, NEG_BIG));
            m = fmaxf(m, fmaxf(fmaxf(x0, x1), fmaxf(x2, x3)));
        }
#pragma unroll 4
        for (int t4 = 0; t4 < 128; t4++) {
            float4 v = vv[t4], tm = tt[t4];
            float x0 = fmaf(a, v.x, fmaf(sm * tm.x, 1e10f, NEG_BIG));
            float x1 = fmaf(a, v.y, fmaf(sm * tm.y, 1e10f, NEG_BIG));
            float x2 = fmaf(a, v.z, fmaf(sm * tm.z, 1e10f, NEG_BIG));
            float x3 = fmaf(a, v.w, fmaf(sm * tm.w, 1e10f, NEG_BIG));
            float e0 = ex2((x0 - m) * LOG2E);
            float e1 = ex2((x1 - m) * LOG2E);
            float e2 = ex2((x2 - m) * LOG2E);
            float e3 = ex2((x3 - m) * LOG2E);
            S += e0 + e1 + e2 + e3;
            A = fmaf(e0, v.x, A);
            A = fmaf(e1, v.y, A);
            A = fmaf(e2, v.z, A);
            A = fmaf(e3, v.w, A);
        }
        c_s[j * Rr + r] = A / S;
    }
    __syncthreads();

    // Phase B: out tile [64 s][512 d] = c . (w * sc)
    {
        int d4 = tid & 127;
        int jg = tid >> 7;   // 0..3
        float4 wv[Rr];
#pragma unroll
        for (int rr = 0; rr < Rr; rr++) {
            float4 ww = ((const float4*)w)[rr * 128 + d4];
            float sc = sc_s[rr];
            ww.x *= sc; ww.y *= sc; ww.z *= sc; ww.w *= sc;
            wv[rr] = ww;
        }

        float4* out4 = (float4*)out;
#pragma unroll
        for (int k = 0; k < 16; k++) {
            int jj = jg + 4 * k;
            float4 o = make_float4(0.f, 0.f, 0.f, 0.f);
#pragma unroll
            for (int rr = 0; rr < Rr; rr++) {
                float c = c_s[jj * Rr + rr];
                o.x = fmaf(c, wv[rr].x, o.x);
                o.y = fmaf(c, wv[rr].y, o.y);
                o.z = fmaf(c, wv[rr].z, o.z);
                o.w = fmaf(c, wv[rr].w, o.w);
            }
            out4[((size_t)b * Ss + s0 + jj) * (Dd / 4) + d4] = o;
        }
    }
}

// ---------------------------------------------------------------------------
extern "C" void kernel_launch(void* const* d_in, const int* in_sizes, int n_in,
                              void* d_out, int out_size) {
    const float* src_emb  = (const float*)d_in[0];
    const float* tar_emb  = (const float*)d_in[1];
    const float* src_mask = (const float*)d_in[2];
    const float* tar_mask = (const float*)d_in[3];
    const float* w        = (const float*)d_in[4];
    float* out            = (float*)d_out;

    k_fused<<<NBLK, 512>>>(src_emb, tar_emb, src_mask, tar_mask, w, out);
}

// round 13
// speedup vs baseline: 1.1913x; 1.1913x over previous
#include <cuda_runtime.h>
#include <cuda_fp16.h>
#include <math.h>

#define Bb 16
#define Ss 512
#define Tt 512
#define Dd 512
#define Rr 8
#define NEG_BIG (-1e10f)
#define LOG2E 1.4426950408889634f

typedef unsigned long long u64;

// scratch (device globals; no allocation allowed)
__device__ float g_sc[Rr];                 // 1/||w_r|| (published by k_dots block 0)
__device__ float g_src_wt[Bb * Rr * Ss];   // [b,r,s]
__device__ float g_tar_wt[Bb * Rr * Tt];   // [b,r,t]

__device__ __forceinline__ float ex2(float x) {
    float y;
    asm("ex2.approx.f32 %0, %1;" : "=f"(y) : "f"(x));
    return y;
}
__device__ __forceinline__ u64 pk(float lo, float hi) {
    u64 d; asm("mov.b64 %0, {%1, %2};" : "=l"(d) : "f"(lo), "f"(hi)); return d;
}
__device__ __forceinline__ void upk(u64 p, float& lo, float& hi) {
    asm("mov.b64 {%0, %1}, %2;" : "=f"(lo), "=f"(hi) : "l"(p));
}
__device__ __forceinline__ u64 ffma2(u64 a, u64 b, u64 c) {
    u64 d; asm("fma.rn.f32x2 %0, %1, %2, %3;" : "=l"(d) : "l"(a), "l"(b), "l"(c)); return d;
}
__device__ __forceinline__ __half2 hex2(__half2 x) {
    unsigned u = *reinterpret_cast<unsigned*>(&x);
    unsigned y;
    asm("ex2.approx.f16x2 %0, %1;" : "=r"(y) : "r"(u));
    return *reinterpret_cast<__half2*>(&y);
}

// ---------------------------------------------------------------------------
// Kernel 1 (R9): dot each embedding row with all 8 RAW w rows; scale by
// 1/||w_r|| at the store. 256 threads, 4 rows/warp, k0 prefetched before the
// w-smem sync, k+1 double-buffered. 512 blocks x 32 rows.
// ---------------------------------------------------------------------------
__global__ __launch_bounds__(256, 2) void k_dots(const float* __restrict__ src,
                                                 const float* __restrict__ tar,
                                                 const float* __restrict__ w) {
    __shared__ float4 wn_s[Rr * Dd / 4];  // 16 KB raw w
    __shared__ float  sc_s[Rr];
    int tid  = threadIdx.x;
    int warp = tid >> 5;
    int lane = tid & 31;

    int base = blockIdx.x * 32 + warp * 4;
    bool is_src = base < Bb * Ss;            // blocks never straddle (8192 % 32 == 0)
    const float* eb = is_src ? src : tar;
    int lbase = is_src ? base : base - Bb * Ss;

    float4 xa[4], xb[4];
#pragma unroll
    for (int rr = 0; rr < 4; rr++)
        xa[rr] = ((const float4*)(eb + (size_t)(lbase + rr) * Dd))[lane];

#pragma unroll
    for (int i = 0; i < 4; i++)
        wn_s[tid + 256 * i] = ((const float4*)w)[tid + 256 * i];
    __syncthreads();

    {
        float ss = 0.f;
#pragma unroll
        for (int k = 0; k < 4; k++) {
            float4 x = wn_s[warp * 128 + lane + 32 * k];
            ss += x.x * x.x + x.y * x.y + x.z * x.z + x.w * x.w;
        }
#pragma unroll
        for (int off = 16; off; off >>= 1)
            ss += __shfl_xor_sync(0xffffffffu, ss, off);
        if (lane == 0) {
            float sc = 1.0f / fmaxf(sqrtf(ss), 1e-12f);
            sc_s[warp] = sc;
            if (blockIdx.x == 0) g_sc[warp] = sc;
        }
    }
    __syncthreads();

    u64 acc2[4][Rr];
#pragma unroll
    for (int rr = 0; rr < 4; rr++)
#pragma unroll
        for (int r = 0; r < Rr; r++) acc2[rr][r] = 0ull;

#pragma unroll
    for (int k = 0; k < 4; k++) {
        if (k < 3) {
#pragma unroll
            for (int rr = 0; rr < 4; rr++)
                xb[rr] = ((const float4*)(eb + (size_t)(lbase + rr) * Dd))[lane + 32 * (k + 1)];
        }
        u64 xp01[4], xp23[4];
#pragma unroll
        for (int rr = 0; rr < 4; rr++) {
            xp01[rr] = pk(xa[rr].x, xa[rr].y);
            xp23[rr] = pk(xa[rr].z, xa[rr].w);
        }
#pragma unroll
        for (int r = 0; r < Rr; r++) {
            float4 wv = wn_s[r * 128 + lane + 32 * k];
            u64 w01 = pk(wv.x, wv.y);
            u64 w23 = pk(wv.z, wv.w);
#pragma unroll
            for (int rr = 0; rr < 4; rr++) {
                acc2[rr][r] = ffma2(xp01[rr], w01, acc2[rr][r]);
                acc2[rr][r] = ffma2(xp23[rr], w23, acc2[rr][r]);
            }
        }
#pragma unroll
        for (int rr = 0; rr < 4; rr++) xa[rr] = xb[rr];
    }

    float t[32];
#pragma unroll
    for (int rr = 0; rr < 4; rr++)
#pragma unroll
        for (int r = 0; r < Rr; r++) {
            float lo, hi;
            upk(acc2[rr][r], lo, hi);
            t[rr * 8 + r] = lo + hi;
        }

#pragma unroll
    for (int st = 0; st < 5; st++) {
        int off = 1 << st;
        int sel = lane & off;
#pragma unroll
        for (int j = 0; j < (16 >> st); j++) {
            float give = sel ? t[2 * j]     : t[2 * j + 1];
            float keep = sel ? t[2 * j + 1] : t[2 * j];
            float recv = __shfl_xor_sync(0xffffffffu, give, off);
            t[j] = keep + recv;
        }
    }

    {
        int rr = lane >> 3, r = lane & 7;
        int gid = lbase + rr;
        int bb = gid >> 9, s = gid & 511;
        float* gw = is_src ? g_src_wt : g_tar_wt;
        gw[((size_t)bb * Rr + r) * Ss + s] = t[0] * sc_s[r];
    }
}

// ---------------------------------------------------------------------------
// Kernel 2 (fused attention + output): grid = B*(S/32) = 256 blocks, 512 thr.
// Preamble now register-side: the v/tm/sm values loaded into registers feed
// the max/min/mask reductions and the vd build directly (no smem re-reads).
// Fast path (all masks 1): vd = v - vmax (or vmin) in smem half2;
// x = a2*vd via HMUL2, exp via ex2.f16x2, fp16 accumulation (16 lanes);
// recover sum(e*v) = sum(e*vd) + vmax*sum(e) exactly in f32.
// Slow path: general two-pass fp32 (block-uniform branch).
// Phase B: out tile [32 s][512 d] = c · (w * g_sc) with w in registers.
// ---------------------------------------------------------------------------
__global__ __launch_bounds__(512, 2) void k_attn_out(const float* __restrict__ src_mask,
                                                     const float* __restrict__ tar_mask,
                                                     const float* __restrict__ w,
                                                     float* __restrict__ out) {
    __shared__ float   v_s[Rr * Tt];        // 16 KB
    __shared__ __half2 vdx_h[Rr * Tt / 2];  // 8 KB: v - vmax[r]
    __shared__ __half2 vdn_h[Rr * Tt / 2];  // 8 KB: v - vmin[r]
    __shared__ float   tm_s[Tt];
    __shared__ float   a_s[Rr * 32];
    __shared__ float   sm_s[32];
    __shared__ float   ps[512], pa[512], pm[512];
    __shared__ float   c_s[32 * Rr];
    __shared__ float   pm_a[16], pn_a[16], pm_b[16], pn_b[16];
    __shared__ float   red_max[Rr], red_min[Rr];
    __shared__ int     red_one[4];

    int b   = blockIdx.x >> 4;
    int s0  = (blockIdx.x & 15) * 32;
    int tid = threadIdx.x;
    int warp = tid >> 5, lane = tid & 31;
    int half = tid >> 8;
    int r    = (tid >> 5) & 7;
    int j    = tid & 31;

    // loads (keep register copies for the reductions/build)
    const float4* vsrc = (const float4*)(g_tar_wt + (size_t)b * Rr * Tt);
    float4 v4a = vsrc[tid];
    float4 v4b = vsrc[tid + 512];
    ((float4*)v_s)[tid]       = v4a;
    ((float4*)v_s)[tid + 512] = v4b;

    float4 tm4 = make_float4(1.f, 1.f, 1.f, 1.f);
    if (tid < 128) {
        tm4 = ((const float4*)(tar_mask + (size_t)b * Tt))[tid];
        ((float4*)tm_s)[tid] = tm4;
    }
    if (tid < 256) a_s[tid] = g_src_wt[((size_t)b * Rr + (tid >> 5)) * Ss + s0 + (tid & 31)];
    float smv = 1.f;
    if (tid < 32) { smv = src_mask[(size_t)b * Ss + s0 + tid]; sm_s[tid] = smv; }

    // register-side partial max/min (v4a -> r_lo = tid>>7, v4b -> r_lo+4)
    {
        float mxa = fmaxf(fmaxf(v4a.x, v4a.y), fmaxf(v4a.z, v4a.w));
        float mna = fminf(fminf(v4a.x, v4a.y), fminf(v4a.z, v4a.w));
        float mxb = fmaxf(fmaxf(v4b.x, v4b.y), fmaxf(v4b.z, v4b.w));
        float mnb = fminf(fminf(v4b.x, v4b.y), fminf(v4b.z, v4b.w));
#pragma unroll
        for (int off = 16; off; off >>= 1) {
            mxa = fmaxf(mxa, __shfl_xor_sync(0xffffffffu, mxa, off));
            mna = fminf(mna, __shfl_xor_sync(0xffffffffu, mna, off));
            mxb = fmaxf(mxb, __shfl_xor_sync(0xffffffffu, mxb, off));
            mnb = fminf(mnb, __shfl_xor_sync(0xffffffffu, mnb, off));
        }
        if (lane == 0) {
            pm_a[warp] = mxa; pn_a[warp] = mna;
            pm_b[warp] = mxb; pn_b[warp] = mnb;
        }
        // register-side mask check (only warps 0..3 carry tm data)
        int ok = 1;
        if (tid < 128) ok = (tm4.x == 1.0f) & (tm4.y == 1.0f) & (tm4.z == 1.0f) & (tm4.w == 1.0f);
        if (tid < 32)  ok &= (smv == 1.0f);
        unsigned bal = __ballot_sync(0xffffffffu, ok);
        if (warp < 4 && lane == 0) red_one[warp] = (bal == 0xffffffffu);
    }
    __syncthreads();

    if (tid < Rr) {
        int rr = tid;
        float mx, mn;
        if (rr < 4) {
            mx = fmaxf(fmaxf(pm_a[4 * rr], pm_a[4 * rr + 1]), fmaxf(pm_a[4 * rr + 2], pm_a[4 * rr + 3]));
            mn = fminf(fminf(pn_a[4 * rr], pn_a[4 * rr + 1]), fminf(pn_a[4 * rr + 2], pn_a[4 * rr + 3]));
        } else {
            int q = rr - 4;
            mx = fmaxf(fmaxf(pm_b[4 * q], pm_b[4 * q + 1]), fmaxf(pm_b[4 * q + 2], pm_b[4 * q + 3]));
            mn = fminf(fminf(pn_b[4 * q], pn_b[4 * q + 1]), fminf(pn_b[4 * q + 2], pn_b[4 * q + 3]));
        }
        red_max[rr] = mx;
        red_min[rr] = mn;
    }
    __syncthreads();

    int fast = red_one[0] & red_one[1] & red_one[2] & red_one[3];

    // build half2 vd arrays from register copies
    {
        int ra = tid >> 7;
        int rb = ra + 4;
        float mxa = red_max[ra], mna = red_min[ra];
        float mxb = red_max[rb], mnb = red_min[rb];
        vdx_h[2 * tid]     = __floats2half2_rn(v4a.x - mxa, v4a.y - mxa);
        vdx_h[2 * tid + 1] = __floats2half2_rn(v4a.z - mxa, v4a.w - mxa);
        vdn_h[2 * tid]     = __floats2half2_rn(v4a.x - mna, v4a.y - mna);
        vdn_h[2 * tid + 1] = __floats2half2_rn(v4a.z - mna, v4a.w - mna);
        int ib = tid + 512;
        vdx_h[2 * ib]      = __floats2half2_rn(v4b.x - mxb, v4b.y - mxb);
        vdx_h[2 * ib + 1]  = __floats2half2_rn(v4b.z - mxb, v4b.w - mxb);
        vdn_h[2 * ib]      = __floats2half2_rn(v4b.x - mnb, v4b.y - mnb);
        vdn_h[2 * ib + 1]  = __floats2half2_rn(v4b.z - mnb, v4b.w - mnb);
    }
    __syncthreads();

    float a = a_s[tid & 255];

    if (fast) {
        const uint4* vp = (const uint4*)((a >= 0.f) ? vdx_h : vdn_h) + r * 64 + half * 32;
        __half2 a2h = __half2half2(__float2half_rn(a * LOG2E));
        __half2 sh[8], qh[8];
#pragma unroll
        for (int i = 0; i < 8; i++) { sh[i] = __half2half2(__ushort_as_half(0)); qh[i] = sh[i]; }

#pragma unroll
        for (int it = 0; it < 32; it += 2) {
            uint4 u0 = vp[it];
            uint4 u1 = vp[it + 1];
            __half2 v0 = *reinterpret_cast<__half2*>(&u0.x);
            __half2 v1 = *reinterpret_cast<__half2*>(&u0.y);
            __half2 v2 = *reinterpret_cast<__half2*>(&u0.z);
            __half2 v3 = *reinterpret_cast<__half2*>(&u0.w);
            __half2 e0 = hex2(__hmul2(a2h, v0));
            __half2 e1 = hex2(__hmul2(a2h, v1));
            __half2 e2 = hex2(__hmul2(a2h, v2));
            __half2 e3 = hex2(__hmul2(a2h, v3));
            sh[0] = __hadd2(sh[0], e0);
            sh[1] = __hadd2(sh[1], e1);
            sh[2] = __hadd2(sh[2], e2);
            sh[3] = __hadd2(sh[3], e3);
            qh[0] = __hfma2(e0, v0, qh[0]);
            qh[1] = __hfma2(e1, v1, qh[1]);
            qh[2] = __hfma2(e2, v2, qh[2]);
            qh[3] = __hfma2(e3, v3, qh[3]);
            __half2 w0 = *reinterpret_cast<__half2*>(&u1.x);
            __half2 w1 = *reinterpret_cast<__half2*>(&u1.y);
            __half2 w2 = *reinterpret_cast<__half2*>(&u1.z);
            __half2 w3 = *reinterpret_cast<__half2*>(&u1.w);
            __half2 f0 = hex2(__hmul2(a2h, w0));
            __half2 f1 = hex2(__hmul2(a2h, w1));
            __half2 f2 = hex2(__hmul2(a2h, w2));
            __half2 f3 = hex2(__hmul2(a2h, w3));
            sh[4] = __hadd2(sh[4], f0);
            sh[5] = __hadd2(sh[5], f1);
            sh[6] = __hadd2(sh[6], f2);
            sh[7] = __hadd2(sh[7], f3);
            qh[4] = __hfma2(f0, w0, qh[4]);
            qh[5] = __hfma2(f1, w1, qh[5]);
            qh[6] = __hfma2(f2, w2, qh[6]);
            qh[7] = __hfma2(f3, w3, qh[7]);
        }
        float S = 0.f, A = 0.f;
#pragma unroll
        for (int i = 0; i < 8; i++) {
            float2 fs = __half22float2(sh[i]);
            float2 fq = __half22float2(qh[i]);
            S += fs.x + fs.y;
            A += fq.x + fq.y;
        }
        ps[tid] = S; pa[tid] = A;
        __syncthreads();
    } else {
        const float4* vv = (const float4*)(v_s + r * Tt) + half * 64;
        const float4* tt = (const float4*)tm_s + half * 64;
        float sm = sm_s[j];
        float sum = 0.f, acc = 0.f;
        float m = -3.4e38f;
#pragma unroll 4
        for (int t4 = 0; t4 < 64; t4++) {
            float4 v = vv[t4], tm = tt[t4];
            float x0 = fmaf(a, v.x, fmaf(sm * tm.x, 1e10f, NEG_BIG));
            float x1 = fmaf(a, v.y, fmaf(sm * tm.y, 1e10f, NEG_BIG));
            float x2 = fmaf(a, v.z, fmaf(sm * tm.z, 1e10f, NEG_BIG));
            float x3 = fmaf(a, v.w, fmaf(sm * tm.w, 1e10f, NEG_BIG));
            m = fmaxf(m, fmaxf(fmaxf(x0, x1), fmaxf(x2, x3)));
        }
        pm[tid] = m;
        __syncthreads();
        m = fmaxf(pm[tid], pm[tid ^ 256]);
#pragma unroll 4
        for (int t4 = 0; t4 < 64; t4++) {
            float4 v = vv[t4], tm = tt[t4];
            float x0 = fmaf(a, v.x, fmaf(sm * tm.x, 1e10f, NEG_BIG));
            float x1 = fmaf(a, v.y, fmaf(sm * tm.y, 1e10f, NEG_BIG));
            float x2 = fmaf(a, v.z, fmaf(sm * tm.z, 1e10f, NEG_BIG));
            float x3 = fmaf(a, v.w, fmaf(sm * tm.w, 1e10f, NEG_BIG));
            float e0 = ex2((x0 - m) * LOG2E);
            float e1 = ex2((x1 - m) * LOG2E);
            float e2 = ex2((x2 - m) * LOG2E);
            float e3 = ex2((x3 - m) * LOG2E);
            sum += e0 + e1 + e2 + e3;
            acc = fmaf(e0, v.x, acc);
            acc = fmaf(e1, v.y, acc);
            acc = fmaf(e2, v.z, acc);
            acc = fmaf(e3, v.w, acc);
        }
        ps[tid] = sum; pa[tid] = acc;
        __syncthreads();
    }

    if (tid < 256) {
        float S = ps[tid] + ps[tid + 256];
        float A = pa[tid] + pa[tid + 256];
        float c = A / S;
        if (fast) {
            float aa = a_s[tid];
            c += (aa >= 0.f) ? red_max[tid >> 5] : red_min[tid >> 5];
        }
        c_s[(tid & 31) * Rr + (tid >> 5)] = c;
    }
    __syncthreads();

    // Phase B: out tile [32 s][512 d] = c · (w * g_sc)
    {
        int d4 = tid & 127;
        int jg = tid >> 7;
        float4 wv[Rr];
#pragma unroll
        for (int rr = 0; rr < Rr; rr++) {
            float4 ww = ((const float4*)w)[rr * 128 + d4];
            float sc = g_sc[rr];
            ww.x *= sc; ww.y *= sc; ww.z *= sc; ww.w *= sc;
            wv[rr] = ww;
        }

        float4* out4 = (float4*)out;
#pragma unroll
        for (int k = 0; k < 8; k++) {
            int jj = jg + 4 * k;
            float4 o = make_float4(0.f, 0.f, 0.f, 0.f);
#pragma unroll
            for (int rr = 0; rr < Rr; rr++) {
                float c = c_s[jj * Rr + rr];
                o.x = fmaf(c, wv[rr].x, o.x);
                o.y = fmaf(c, wv[rr].y, o.y);
                o.z = fmaf(c, wv[rr].z, o.z);
                o.w = fmaf(c, wv[rr].w, o.w);
            }
            out4[((size_t)b * Ss + s0 + jj) * (Dd / 4) + d4] = o;
        }
    }
}

// ---------------------------------------------------------------------------
extern "C" void kernel_launch(void* const* d_in, const int* in_sizes, int n_in,
                              void* d_out, int out_size) {
    const float* src_emb  = (const float*)d_in[0];
    const float* tar_emb  = (const float*)d_in[1];
    const float* src_mask = (const float*)d_in[2];
    const float* tar_mask = (const float*)d_in[3];
    const float* w        = (const float*)d_in[4];
    float* out            = (float*)d_out;

    k_dots<<<(Bb * Ss + Bb * Tt) / 32, 256>>>(src_emb, tar_emb, w);
    k_attn_out<<<Bb * (Ss / 32), 512>>>(src_mask, tar_mask, w, out);
}

// round 14
// speedup vs baseline: 1.1931x; 1.0015x over previous
#include <cuda_runtime.h>
#include <math.h>

#define Bb 16
#define Ss 512
#define Tt 512
#define Dd 512
#define Rr 8
#define NEG_BIG (-1e10f)
#define LOG2E 1.4426950408889634f
#define NNODE 128

typedef unsigned long long u64;

// scratch (device globals; no allocation allowed)
__device__ float  g_sc[Rr];                  // 1/||w_r||
__device__ float  g_src_wt[Bb * Rr * Ss];    // [b,r,s]
__device__ float  g_tar_wt[Bb * Rr * Tt];    // [b,r,t]
__device__ float  g_tab[Bb * Rr * NNODE];    // c(a) tables
__device__ float2 g_meta[Bb * Rr];           // (g0, 1/h) per (b,r)

__device__ __forceinline__ float ex2(float x) {
    float y;
    asm("ex2.approx.f32 %0, %1;" : "=f"(y) : "f"(x));
    return y;
}
__device__ __forceinline__ u64 pk(float lo, float hi) {
    u64 d; asm("mov.b64 %0, {%1, %2};" : "=l"(d) : "f"(lo), "f"(hi)); return d;
}
__device__ __forceinline__ void upk(u64 p, float& lo, float& hi) {
    asm("mov.b64 {%0, %1}, %2;" : "=f"(lo), "=f"(hi) : "l"(p));
}
__device__ __forceinline__ u64 ffma2(u64 a, u64 b, u64 c) {
    u64 d; asm("fma.rn.f32x2 %0, %1, %2, %3;" : "=l"(d) : "l"(a), "l"(b), "l"(c)); return d;
}

// ---------------------------------------------------------------------------
// Kernel 1 (unchanged R9): dots of every embedding row with all 8 raw w rows,
// scaled by 1/||w_r|| at the store. 512 blocks x 32 rows, 256 threads.
// ---------------------------------------------------------------------------
__global__ __launch_bounds__(256, 2) void k_dots(const float* __restrict__ src,
                                                 const float* __restrict__ tar,
                                                 const float* __restrict__ w) {
    __shared__ float4 wn_s[Rr * Dd / 4];  // 16 KB raw w
    __shared__ float  sc_s[Rr];
    int tid  = threadIdx.x;
    int warp = tid >> 5;
    int lane = tid & 31;

    int base = blockIdx.x * 32 + warp * 4;
    bool is_src = base < Bb * Ss;            // blocks never straddle (8192 % 32 == 0)
    const float* eb = is_src ? src : tar;
    int lbase = is_src ? base : base - Bb * Ss;

    float4 xa[4], xb[4];
#pragma unroll
    for (int rr = 0; rr < 4; rr++)
        xa[rr] = ((const float4*)(eb + (size_t)(lbase + rr) * Dd))[lane];

#pragma unroll
    for (int i = 0; i < 4; i++)
        wn_s[tid + 256 * i] = ((const float4*)w)[tid + 256 * i];
    __syncthreads();

    {
        float ss = 0.f;
#pragma unroll
        for (int k = 0; k < 4; k++) {
            float4 x = wn_s[warp * 128 + lane + 32 * k];
            ss += x.x * x.x + x.y * x.y + x.z * x.z + x.w * x.w;
        }
#pragma unroll
        for (int off = 16; off; off >>= 1)
            ss += __shfl_xor_sync(0xffffffffu, ss, off);
        if (lane == 0) {
            float sc = 1.0f / fmaxf(sqrtf(ss), 1e-12f);
            sc_s[warp] = sc;
            if (blockIdx.x == 0) g_sc[warp] = sc;
        }
    }
    __syncthreads();

    u64 acc2[4][Rr];
#pragma unroll
    for (int rr = 0; rr < 4; rr++)
#pragma unroll
        for (int r = 0; r < Rr; r++) acc2[rr][r] = 0ull;

#pragma unroll
    for (int k = 0; k < 4; k++) {
        if (k < 3) {
#pragma unroll
            for (int rr = 0; rr < 4; rr++)
                xb[rr] = ((const float4*)(eb + (size_t)(lbase + rr) * Dd))[lane + 32 * (k + 1)];
        }
        u64 xp01[4], xp23[4];
#pragma unroll
        for (int rr = 0; rr < 4; rr++) {
            xp01[rr] = pk(xa[rr].x, xa[rr].y);
            xp23[rr] = pk(xa[rr].z, xa[rr].w);
        }
#pragma unroll
        for (int r = 0; r < Rr; r++) {
            float4 wv = wn_s[r * 128 + lane + 32 * k];
            u64 w01 = pk(wv.x, wv.y);
            u64 w23 = pk(wv.z, wv.w);
#pragma unroll
            for (int rr = 0; rr < 4; rr++) {
                acc2[rr][r] = ffma2(xp01[rr], w01, acc2[rr][r]);
                acc2[rr][r] = ffma2(xp23[rr], w23, acc2[rr][r]);
            }
        }
#pragma unroll
        for (int rr = 0; rr < 4; rr++) xa[rr] = xb[rr];
    }

    float t[32];
#pragma unroll
    for (int rr = 0; rr < 4; rr++)
#pragma unroll
        for (int r = 0; r < Rr; r++) {
            float lo, hi;
            upk(acc2[rr][r], lo, hi);
            t[rr * 8 + r] = lo + hi;
        }

#pragma unroll
    for (int st = 0; st < 5; st++) {
        int off = 1 << st;
        int sel = lane & off;
#pragma unroll
        for (int j = 0; j < (16 >> st); j++) {
            float give = sel ? t[2 * j]     : t[2 * j + 1];
            float keep = sel ? t[2 * j + 1] : t[2 * j];
            float recv = __shfl_xor_sync(0xffffffffu, give, off);
            t[j] = keep + recv;
        }
    }

    {
        int rr = lane >> 3, r = lane & 7;
        int gid = lbase + rr;
        int bb = gid >> 9, s = gid & 511;
        float* gw = is_src ? g_src_wt : g_tar_wt;
        gw[((size_t)bb * Rr + r) * Ss + s] = t[0] * sc_s[r];
    }
}

// ---------------------------------------------------------------------------
// Kernel 2 (NEW): build c(a) interpolation tables. Grid = B*R = 128 blocks,
// 512 threads. Per block (b,r): find [amin,amax] of a-row and vmax/vmin of
// v-row; evaluate c(a_n) = sum_t e^{a_n v_t} v_t / sum_t e^{a_n v_t} at 128
// uniform nodes (shift by a_n*vref for range safety; ratio is shift-exact).
// Thread (node=tid>>2, sub=tid&3) covers t = 4i+sub (conflict-free LDS).
// ---------------------------------------------------------------------------
__global__ __launch_bounds__(512, 2) void k_tab() {
    __shared__ float v_s[Tt];
    __shared__ float red[4][16];
    __shared__ float s_amin, s_amax, s_vmin, s_vmax;

    int tid  = threadIdx.x;
    int warp = tid >> 5;
    int lane = tid & 31;
    int br   = blockIdx.x;                  // b*Rr + r

    float a_val = g_src_wt[(size_t)br * Ss + tid];
    float v_val = g_tar_wt[(size_t)br * Tt + tid];
    v_s[tid] = v_val;

    float amn = a_val, amx = a_val, vmn = v_val, vmx = v_val;
#pragma unroll
    for (int off = 16; off; off >>= 1) {
        amn = fminf(amn, __shfl_xor_sync(0xffffffffu, amn, off));
        amx = fmaxf(amx, __shfl_xor_sync(0xffffffffu, amx, off));
        vmn = fminf(vmn, __shfl_xor_sync(0xffffffffu, vmn, off));
        vmx = fmaxf(vmx, __shfl_xor_sync(0xffffffffu, vmx, off));
    }
    if (lane == 0) {
        red[0][warp] = amn; red[1][warp] = amx;
        red[2][warp] = vmn; red[3][warp] = vmx;
    }
    __syncthreads();
    if (warp == 0) {
        int li = (lane < 16) ? lane : 0;
        float t0 = red[0][li], t1 = red[1][li], t2 = red[2][li], t3 = red[3][li];
#pragma unroll
        for (int off = 8; off; off >>= 1) {
            t0 = fminf(t0, __shfl_xor_sync(0xffffffffu, t0, off));
            t1 = fmaxf(t1, __shfl_xor_sync(0xffffffffu, t1, off));
            t2 = fminf(t2, __shfl_xor_sync(0xffffffffu, t2, off));
            t3 = fmaxf(t3, __shfl_xor_sync(0xffffffffu, t3, off));
        }
        if (lane == 0) { s_amin = t0; s_amax = t1; s_vmin = t2; s_vmax = t3; }
    }
    __syncthreads();

    float amin = s_amin, amax = s_amax;
    float h  = (amax - amin) * (1.0f / 123.0f) + 1e-20f;
    float g0 = amin - 2.0f * h;

    int node = tid >> 2, sub = tid & 3;
    float an   = fmaf((float)node, h, g0);
    float vref = (an >= 0.f) ? s_vmax : s_vmin;
    float a2   = an * LOG2E;
    float nm2  = -a2 * vref;                // x = a2*(v - vref) <= 0

    float S0 = 0.f, S1 = 0.f, A0 = 0.f, A1 = 0.f;
#pragma unroll 8
    for (int i = 0; i < 128; i += 2) {
        float va = v_s[4 * i + sub];
        float vb = v_s[4 * (i + 1) + sub];
        float ea = ex2(fmaf(a2, va, nm2));
        float eb = ex2(fmaf(a2, vb, nm2));
        S0 += ea; S1 += eb;
        A0 = fmaf(ea, va, A0);
        A1 = fmaf(eb, vb, A1);
    }
    float S = S0 + S1, A = A0 + A1;
    S += __shfl_xor_sync(0xffffffffu, S, 1);
    A += __shfl_xor_sync(0xffffffffu, A, 1);
    S += __shfl_xor_sync(0xffffffffu, S, 2);
    A += __shfl_xor_sync(0xffffffffu, A, 2);

    if (sub == 0) g_tab[(size_t)br * NNODE + node] = A / S;
    if (tid == 0) g_meta[br] = make_float2(g0, 1.0f / h);
}

// ---------------------------------------------------------------------------
// Kernel 3 (fused attention + output): grid = B*(S/32) = 256 blocks, 512 thr.
// Fast path (all masks 1): Catmull-Rom interpolation of the c(a) table —
// no exps at all. Slow path: general two-pass fp32 softmax (block-uniform).
// Phase B: out tile [32 s][512 d] = c · (w * g_sc) with w in registers.
// ---------------------------------------------------------------------------
__global__ __launch_bounds__(512, 2) void k_attn_out(const float* __restrict__ src_mask,
                                                     const float* __restrict__ tar_mask,
                                                     const float* __restrict__ w,
                                                     float* __restrict__ out) {
    __shared__ float   v_s[Rr * Tt];        // 16 KB (slow path)
    __shared__ float   tm_s[Tt];
    __shared__ float   a_s[Rr * 32];
    __shared__ float   sm_s[32];
    __shared__ float   tab_s[Rr * NNODE];   // 4 KB
    __shared__ float2  meta_s[Rr];
    __shared__ float   ps[512], pa[512], pm[512];
    __shared__ float   c_s[32 * Rr];
    __shared__ int     red_one[4];

    int b   = blockIdx.x >> 4;
    int s0  = (blockIdx.x & 15) * 32;
    int tid = threadIdx.x;
    int warp = tid >> 5, lane = tid & 31;
    int half = tid >> 8;
    int r    = (tid >> 5) & 7;
    int j    = tid & 31;

    const float4* vsrc = (const float4*)(g_tar_wt + (size_t)b * Rr * Tt);
    ((float4*)v_s)[tid]       = vsrc[tid];
    ((float4*)v_s)[tid + 512] = vsrc[tid + 512];

    tab_s[tid]       = g_tab[(size_t)b * Rr * NNODE + tid];
    tab_s[tid + 512] = g_tab[(size_t)b * Rr * NNODE + tid + 512];
    if (tid < Rr) meta_s[tid] = g_meta[b * Rr + tid];

    float4 tm4 = make_float4(1.f, 1.f, 1.f, 1.f);
    if (tid < 128) {
        tm4 = ((const float4*)(tar_mask + (size_t)b * Tt))[tid];
        ((float4*)tm_s)[tid] = tm4;
    }
    if (tid < 256) a_s[tid] = g_src_wt[((size_t)b * Rr + (tid >> 5)) * Ss + s0 + (tid & 31)];
    float smv = 1.f;
    if (tid < 32) { smv = src_mask[(size_t)b * Ss + s0 + tid]; sm_s[tid] = smv; }

    {
        int ok = 1;
        if (tid < 128) ok = (tm4.x == 1.0f) & (tm4.y == 1.0f) & (tm4.z == 1.0f) & (tm4.w == 1.0f);
        if (tid < 32)  ok &= (smv == 1.0f);
        unsigned bal = __ballot_sync(0xffffffffu, ok);
        if (warp < 4 && lane == 0) red_one[warp] = (bal == 0xffffffffu);
    }
    __syncthreads();

    int fast = red_one[0] & red_one[1] & red_one[2] & red_one[3];

    if (fast) {
        if (tid < 256) {
            float a = a_s[tid];
            float2 mt = meta_s[r];
            float u = (a - mt.x) * mt.y;
            u = fminf(fmaxf(u, 2.0f), 125.0f);
            int k = (int)u;
            float f = u - (float)k;
            const float* tp = tab_s + r * NNODE + k;
            float p0 = tp[-1], p1 = tp[0], p2 = tp[1], p3 = tp[2];
            float c = p1 + 0.5f * f * ((p2 - p0)
                    + f * ((2.f * p0 - 5.f * p1 + 4.f * p2 - p3)
                    + f * (3.f * (p1 - p2) + p3 - p0)));
            c_s[j * Rr + r] = c;
        }
        __syncthreads();
    } else {
        const float4* vv = (const float4*)(v_s + r * Tt) + half * 64;
        const float4* tt = (const float4*)tm_s + half * 64;
        float a  = a_s[tid & 255];
        float sm = sm_s[j];
        float sum = 0.f, acc = 0.f;
        float m = -3.4e38f;
#pragma unroll 4
        for (int t4 = 0; t4 < 64; t4++) {
            float4 v = vv[t4], tm = tt[t4];
            float x0 = fmaf(a, v.x, fmaf(sm * tm.x, 1e10f, NEG_BIG));
            float x1 = fmaf(a, v.y, fmaf(sm * tm.y, 1e10f, NEG_BIG));
            float x2 = fmaf(a, v.z, fmaf(sm * tm.z, 1e10f, NEG_BIG));
            float x3 = fmaf(a, v.w, fmaf(sm * tm.w, 1e10f, NEG_BIG));
            m = fmaxf(m, fmaxf(fmaxf(x0, x1), fmaxf(x2, x3)));
        }
        pm[tid] = m;
        __syncthreads();
        m = fmaxf(pm[tid], pm[tid ^ 256]);
#pragma unroll 4
        for (int t4 = 0; t4 < 64; t4++) {
            float4 v = vv[t4], tm = tt[t4];
            float x0 = fmaf(a, v.x, fmaf(sm * tm.x, 1e10f, NEG_BIG));
            float x1 = fmaf(a, v.y, fmaf(sm * tm.y, 1e10f, NEG_BIG));
            float x2 = fmaf(a, v.z, fmaf(sm * tm.z, 1e10f, NEG_BIG));
            float x3 = fmaf(a, v.w, fmaf(sm * tm.w, 1e10f, NEG_BIG));
            float e0 = ex2((x0 - m) * LOG2E);
            float e1 = ex2((x1 - m) * LOG2E);
            float e2 = ex2((x2 - m) * LOG2E);
            float e3 = ex2((x3 - m) * LOG2E);
            sum += e0 + e1 + e2 + e3;
            acc = fmaf(e0, v.x, acc);
            acc = fmaf(e1, v.y, acc);
            acc = fmaf(e2, v.z, acc);
            acc = fmaf(e3, v.w, acc);
        }
        ps[tid] = sum; pa[tid] = acc;
        __syncthreads();
        if (tid < 256) {
            float S = ps[tid] + ps[tid + 256];
            float A = pa[tid] + pa[tid + 256];
            c_s[(tid & 31) * Rr + (tid >> 5)] = A / S;
        }
        __syncthreads();
    }

    // Phase B: out tile [32 s][512 d] = c · (w * g_sc)
    {
        int d4 = tid & 127;
        int jg = tid >> 7;
        float4 wv[Rr];
#pragma unroll
        for (int rr = 0; rr < Rr; rr++) {
            float4 ww = ((const float4*)w)[rr * 128 + d4];
            float sc = g_sc[rr];
            ww.x *= sc; ww.y *= sc; ww.z *= sc; ww.w *= sc;
            wv[rr] = ww;
        }

        float4* out4 = (float4*)out;
#pragma unroll
        for (int k = 0; k < 8; k++) {
            int jj = jg + 4 * k;
            float4 o = make_float4(0.f, 0.f, 0.f, 0.f);
#pragma unroll
            for (int rr = 0; rr < Rr; rr++) {
                float c = c_s[jj * Rr + rr];
                o.x = fmaf(c, wv[rr].x, o.x);
                o.y = fmaf(c, wv[rr].y, o.y);
                o.z = fmaf(c, wv[rr].z, o.z);
                o.w = fmaf(c, wv[rr].w, o.w);
            }
            out4[((size_t)b * Ss + s0 + jj) * (Dd / 4) + d4] = o;
        }
    }
}

// ---------------------------------------------------------------------------
extern "C" void kernel_launch(void* const* d_in, const int* in_sizes, int n_in,
                              void* d_out, int out_size) {
    const float* src_emb  = (const float*)d_in[0];
    const float* tar_emb  = (const float*)d_in[1];
    const float* src_mask = (const float*)d_in[2];
    const float* tar_mask = (const float*)d_in[3];
    const float* w        = (const float*)d_in[4];
    float* out            = (float*)d_out;

    k_dots<<<(Bb * Ss + Bb * Tt) / 32, 256>>>(src_emb, tar_emb, w);
    k_tab<<<Bb * Rr, 512>>>();
    k_attn_out<<<Bb * (Ss / 32), 512>>>(src_mask, tar_mask, w, out);
}